// round 5
// baseline (speedup 1.0000x reference)
#include <cuda_runtime.h>

// SNN forward scan: rows = B*N = 65536 independent length-512 recurrences.
// ONE WARP PER BLOCK: 32 threads handle 32 rows; grid = 2048 (near-perfect
// balance, ~14 fully independent pipelines per SM, warp-local sync only).
// Smem-staged, 3-buffer depth-2 cp.async pipeline, coalesced 128B traffic.
// Refractory window as multiplicative mask: ic = x * (1-s[t-1])*(1-s[t-2]).

#define T_STEPS 512
#define CHUNK   32
#define ROWS    32                // threads per block == rows per block
#define NCHUNK  (T_STEPS / CHUNK) // 16
#define STRIDE  36                // padded smem row stride (floats)
#define NBUF    3

__device__ __forceinline__ void cp_async16(float* smem_dst, const float* gmem_src) {
    unsigned saddr = (unsigned)__cvta_generic_to_shared(smem_dst);
    asm volatile("cp.async.cg.shared.global [%0], [%1], 16;\n"
                 :: "r"(saddr), "l"(gmem_src));
}

__global__ __launch_bounds__(ROWS) void snn_fwd_kernel(
    const float* __restrict__ x,
    const float* __restrict__ beta,
    const float* __restrict__ p,
    const float* __restrict__ b,
    float* __restrict__ out,
    int N)
{
    __shared__ float tile[NBUF][ROWS * STRIDE];

    const int tid = threadIdx.x;
    const size_t row_base = (size_t)blockIdx.x * ROWS;
    const int n = (int)((row_base + tid) % (size_t)N);

    // clamped effective per-neuron params
    const float beta_c = fminf(fmaxf(beta[n], 0.001f), 0.999f);
    const float p_c    = fminf(fabsf(p[n]), 0.999f);
    const float b_c    = fminf(fmaxf(fabsf(b[n]), 0.001f), 1.0f);

    // recurrence state
    float mem = 0.0f, a = 0.0f, vth = 1.0f;
    float m1 = 1.0f, m2 = 1.0f;   // 1 - s(t-1), 1 - s(t-2)

    // cooperative addressing: g = k*ROWS + tid, g in [0, 256):
    // r = g>>3 (row), c4 = g&7 (16B slot); 8 consecutive threads cover
    // one row-chunk's 128 B -> fully coalesced lines.

    // preload chunks 0 and 1
    #pragma unroll
    for (int cc = 0; cc < 2; ++cc) {
        #pragma unroll
        for (int k = 0; k < 8; ++k) {
            const int g = k * ROWS + tid;
            const int r = g >> 3, c4 = g & 7;
            cp_async16(&tile[cc][r * STRIDE + c4 * 4],
                       x + (row_base + r) * T_STEPS + cc * CHUNK + c4 * 4);
        }
        asm volatile("cp.async.commit_group;\n");
    }

    for (int c = 0; c < NCHUNK; ++c) {
        const int buf = c % NBUF;

        if (c + 1 < NCHUNK) asm volatile("cp.async.wait_group 1;\n");
        else                asm volatile("cp.async.wait_group 0;\n");
        __syncwarp();   // chunk c visible warp-wide; buffer (c+2)%NBUF free

        // prefetch chunk c+2 (keeps 2 chunk-loads in flight)
        if (c + 2 < NCHUNK) {
            const int buf2 = (c + 2) % NBUF;
            #pragma unroll
            for (int k = 0; k < 8; ++k) {
                const int g = k * ROWS + tid;
                const int r = g >> 3, c4 = g & 7;
                cp_async16(&tile[buf2][r * STRIDE + c4 * 4],
                           x + (row_base + r) * T_STEPS + (c + 2) * CHUNK + c4 * 4);
            }
            asm volatile("cp.async.commit_group;\n");
        }

        // compute: each thread owns one smem row; overwrite x with spikes
        float* rowp = &tile[buf][tid * STRIDE];
        #pragma unroll
        for (int i = 0; i < CHUNK / 4; ++i) {
            float4 xv = *reinterpret_cast<float4*>(rowp + i * 4);
            float4 ov;
            #pragma unroll
            for (int k = 0; k < 4; ++k) {
                const float xt = (k == 0) ? xv.x : (k == 1) ? xv.y
                               : (k == 2) ? xv.z : xv.w;
                const float ic = xt * (m1 * m2);          // refractory mask
                const float nm = fmaf(mem, beta_c, ic);   // leaky integrate
                const float ns = (nm > vth) ? 0.0f : 1.0f;
                const float s  = 1.0f - ns;
                mem = nm * ns;                            // reset-to-zero
                a   = fmaf(p_c, a, s);                    // adaptation
                vth = fmaf(b_c, a, 1.0f);
                m2 = m1; m1 = ns;
                if (k == 0) ov.x = s; else if (k == 1) ov.y = s;
                else if (k == 2) ov.z = s; else ov.w = s;
            }
            *reinterpret_cast<float4*>(rowp + i * 4) = ov;
        }
        __syncwarp();   // spikes visible warp-wide for cooperative store

        // cooperative coalesced streaming store
        #pragma unroll
        for (int k = 0; k < 8; ++k) {
            const int g = k * ROWS + tid;
            const int r = g >> 3, c4 = g & 7;
            const float4 v = *reinterpret_cast<const float4*>(
                &tile[buf][r * STRIDE + c4 * 4]);
            __stcs(reinterpret_cast<float4*>(
                out + (row_base + r) * T_STEPS + c * CHUNK + c4 * 4), v);
        }
        // buffer reuse gated by wait_group + __syncwarp at top of c+1
    }
}

extern "C" void kernel_launch(void* const* d_in, const int* in_sizes, int n_in,
                              void* d_out, int out_size)
{
    const float* x    = (const float*)d_in[0];
    const float* beta = (const float*)d_in[1];
    const float* p    = (const float*)d_in[2];
    const float* b    = (const float*)d_in[3];
    float* out        = (float*)d_out;

    const int N    = in_sizes[1];               // 1024
    const int rows = in_sizes[0] / T_STEPS;     // B*N = 65536

    const int blocks = rows / ROWS;             // 2048
    snn_fwd_kernel<<<blocks, ROWS>>>(x, beta, p, b, out, N);
}

// round 6
// speedup vs baseline: 1.0202x; 1.0202x over previous
#include <cuda_runtime.h>

// SNN forward scan: rows = B*N = 65536 independent length-512 recurrences.
// One warp per block, 32 rows/warp. CHUNK=64 timesteps -> 8 KB contiguous
// read/write bursts per warp, double-buffered cp.async (issue-then-wait so
// 8-16 KB stays in flight). 8 pipeline iterations total (half the syncs of
// the 32-step version). Refractory window as multiplicative mask:
// ic(t) = x(t) * (1-s(t-1)) * (1-s(t-2)).

#define T_STEPS 512
#define CHUNK   64
#define ROWS    32                // threads per block == rows per block
#define NCHUNK  (T_STEPS / CHUNK) // 8
#define STRIDE  68                // padded smem row stride (floats), conflict-free
#define NBUF    2
#define LDI     16                // cp.async iters per chunk: ROWS*CHUNK/ (32*4)

__device__ __forceinline__ void cp_async16(float* smem_dst, const float* gmem_src) {
    unsigned saddr = (unsigned)__cvta_generic_to_shared(smem_dst);
    asm volatile("cp.async.cg.shared.global [%0], [%1], 16;\n"
                 :: "r"(saddr), "l"(gmem_src));
}

__global__ __launch_bounds__(ROWS) void snn_fwd_kernel(
    const float* __restrict__ x,
    const float* __restrict__ beta,
    const float* __restrict__ p,
    const float* __restrict__ b,
    float* __restrict__ out,
    int N)
{
    __shared__ float tile[NBUF][ROWS * STRIDE];

    const int tid = threadIdx.x;
    const size_t row_base = (size_t)blockIdx.x * ROWS;
    const int n = (int)((row_base + tid) % (size_t)N);

    // clamped effective per-neuron params
    const float beta_c = fminf(fmaxf(beta[n], 0.001f), 0.999f);
    const float p_c    = fminf(fabsf(p[n]), 0.999f);
    const float b_c    = fminf(fmaxf(fabsf(b[n]), 0.001f), 1.0f);

    // recurrence state
    float mem = 0.0f, a = 0.0f, vth = 1.0f;
    float m1 = 1.0f, m2 = 1.0f;   // 1 - s(t-1), 1 - s(t-2)

    // cooperative addressing: g = k*32 + tid, g in [0, 512):
    // r = g>>4 (row), c4 = g&15 (16B slot within 64-step row chunk);
    // 16 consecutive threads cover one row-chunk's 256 B (2 lines, coalesced).

    // preload chunk 0
    #pragma unroll
    for (int k = 0; k < LDI; ++k) {
        const int g = k * ROWS + tid;
        const int r = g >> 4, c4 = g & 15;
        cp_async16(&tile[0][r * STRIDE + c4 * 4],
                   x + (row_base + r) * T_STEPS + c4 * 4);
    }
    asm volatile("cp.async.commit_group;\n");

    for (int c = 0; c < NCHUNK; ++c) {
        const int buf = c & 1;

        // issue next chunk's load FIRST (keeps a group in flight during wait)
        if (c + 1 < NCHUNK) {
            #pragma unroll
            for (int k = 0; k < LDI; ++k) {
                const int g = k * ROWS + tid;
                const int r = g >> 4, c4 = g & 15;
                cp_async16(&tile[buf ^ 1][r * STRIDE + c4 * 4],
                           x + (row_base + r) * T_STEPS + (c + 1) * CHUNK + c4 * 4);
            }
            asm volatile("cp.async.commit_group;\n");
            asm volatile("cp.async.wait_group 1;\n");   // chunk c arrived
        } else {
            asm volatile("cp.async.wait_group 0;\n");
        }
        __syncwarp();

        // compute: each thread owns one smem row; overwrite x with spikes
        float* rowp = &tile[buf][tid * STRIDE];
        #pragma unroll
        for (int i = 0; i < CHUNK / 4; ++i) {
            float4 xv = *reinterpret_cast<float4*>(rowp + i * 4);
            float4 ov;
            #pragma unroll
            for (int k = 0; k < 4; ++k) {
                const float xt = (k == 0) ? xv.x : (k == 1) ? xv.y
                               : (k == 2) ? xv.z : xv.w;
                const float ic = xt * (m1 * m2);          // refractory mask
                const float nm = fmaf(mem, beta_c, ic);   // leaky integrate
                const float ns = (nm > vth) ? 0.0f : 1.0f;
                const float s  = 1.0f - ns;
                mem = nm * ns;                            // reset-to-zero
                a   = fmaf(p_c, a, s);                    // adaptation
                vth = fmaf(b_c, a, 1.0f);
                m2 = m1; m1 = ns;
                if (k == 0) ov.x = s; else if (k == 1) ov.y = s;
                else if (k == 2) ov.z = s; else ov.w = s;
            }
            *reinterpret_cast<float4*>(rowp + i * 4) = ov;
        }
        __syncwarp();   // spikes visible warp-wide for cooperative store

        // cooperative coalesced streaming store (8 KB contiguous burst)
        #pragma unroll
        for (int k = 0; k < LDI; ++k) {
            const int g = k * ROWS + tid;
            const int r = g >> 4, c4 = g & 15;
            const float4 v = *reinterpret_cast<const float4*>(
                &tile[buf][r * STRIDE + c4 * 4]);
            __stcs(reinterpret_cast<float4*>(
                out + (row_base + r) * T_STEPS + c * CHUNK + c4 * 4), v);
        }
        __syncwarp();   // buffer 'buf' free before iteration c+1 reuses it
    }
}

extern "C" void kernel_launch(void* const* d_in, const int* in_sizes, int n_in,
                              void* d_out, int out_size)
{
    const float* x    = (const float*)d_in[0];
    const float* beta = (const float*)d_in[1];
    const float* p    = (const float*)d_in[2];
    const float* b    = (const float*)d_in[3];
    float* out        = (float*)d_out;

    const int N    = in_sizes[1];               // 1024
    const int rows = in_sizes[0] / T_STEPS;     // B*N = 65536

    const int blocks = rows / ROWS;             // 2048
    snn_fwd_kernel<<<blocks, ROWS>>>(x, beta, p, b, out, N);
}